// round 1
// baseline (speedup 1.0000x reference)
#include <cuda_runtime.h>

#define BATCH 2
#define SEQ   1024
#define DM    1024
#define HEADS 8
#define DV    128

typedef unsigned long long u64;

// ---------------- scratch (static device arrays; no allocation) ----------------
__device__ float g_Q[BATCH * SEQ * DM];   // Q projection, flat (b, s, dm)
__device__ float g_K[BATCH * SEQ * DV];
__device__ float g_V[BATCH * SEQ * DV];
__device__ float g_O[BATCH * SEQ * DM];   // attention out, flat (b, h, qi, d) == (b, s, dm) view

// ---------------- f32x2 helpers (full-rate fp32 on Blackwell) ----------------
__device__ __forceinline__ u64 pack2(float x) {
    u64 r; asm("mov.b64 %0, {%1, %1};" : "=l"(r) : "f"(x)); return r;
}
__device__ __forceinline__ void ffma2(u64 &c, u64 a, u64 b) {
    asm("fma.rn.f32x2 %0, %1, %2, %0;" : "+l"(c) : "l"(a), "l"(b));
}
__device__ __forceinline__ void fmul2(u64 &c, u64 a) {
    asm("mul.rn.f32x2 %0, %1, %0;" : "+l"(c) : "l"(a));
}
__device__ __forceinline__ float2 unpack2(u64 v) {
    float lo, hi; asm("mov.b64 {%0, %1}, %2;" : "=f"(lo), "=f"(hi) : "l"(v));
    return make_float2(lo, hi);
}
__device__ __forceinline__ float fast_exp2(float x) {
    float y; asm("ex2.approx.f32 %0, %1;" : "=f"(y) : "f"(x)); return y;
}

// ---------------- generic 64x128 SGEMM tile: C = A*B + bias ----------------
// A row-major (lda), B row-major (ldb), C row-major (ldc). K multiple of 8.
// 256 threads; thread (ty,tx) owns rows m0+ty*4..+3, cols n0+{tx*4..+3, 64+tx*4..+3}.
__device__ __forceinline__ void sgemm_tile_64x128(
    const float* __restrict__ A, int lda,
    const float* __restrict__ B, int ldb,
    const float* __restrict__ bias,
    float* __restrict__ C, int ldc,
    int m0, int n0, int K)
{
    __shared__ float As[8][68];    // k-major, transposed A tile (pad 68: conflict-free)
    __shared__ float Bs[8][128];   // k-major, direct B tile

    const int tid = threadIdx.x;
    const int tx = tid & 15, ty = tid >> 4;
    const int ar = tid >> 1, ac4 = (tid & 1) * 4;       // A loader: row, k-quad
    const int br = tid >> 5, bc = (tid & 31) * 4;       // B loader: k, n-quad
    const bool aAct = tid < 128;                        // 64 rows x 2 loaders

    const float* Aptr = A + (size_t)(m0 + ar) * lda + ac4;
    const float* Bptr = B + (size_t)br * ldb + n0 + bc;

    u64 acc[4][4];
    #pragma unroll
    for (int r = 0; r < 4; r++)
        #pragma unroll
        for (int c = 0; c < 4; c++) acc[r][c] = 0ull;

    float4 aPre = make_float4(0.f, 0.f, 0.f, 0.f), bPre;
    if (aAct) aPre = *(const float4*)Aptr;
    bPre = *(const float4*)Bptr;

    const int nk = K >> 3;
    for (int kt = 0; kt < nk; kt++) {
        if (aAct) {
            As[ac4 + 0][ar] = aPre.x; As[ac4 + 1][ar] = aPre.y;
            As[ac4 + 2][ar] = aPre.z; As[ac4 + 3][ar] = aPre.w;
        }
        *(float4*)&Bs[br][bc] = bPre;
        __syncthreads();
        if (kt + 1 < nk) {                 // prefetch next k-tile (overlaps compute)
            if (aAct) aPre = *(const float4*)(Aptr + (kt + 1) * 8);
            bPre = *(const float4*)(Bptr + (size_t)(kt + 1) * 8 * ldb);
        }
        #pragma unroll
        for (int k = 0; k < 8; k++) {
            float a[4];
            *(float4*)a = *(const float4*)&As[k][ty * 4];
            ulonglong2 b0 = *(const ulonglong2*)&Bs[k][tx * 4];
            ulonglong2 b1 = *(const ulonglong2*)&Bs[k][64 + tx * 4];
            #pragma unroll
            for (int r = 0; r < 4; r++) {
                u64 av = pack2(a[r]);
                ffma2(acc[r][0], av, b0.x);
                ffma2(acc[r][1], av, b0.y);
                ffma2(acc[r][2], av, b1.x);
                ffma2(acc[r][3], av, b1.y);
            }
        }
        __syncthreads();
    }

    float4 bs0 = *(const float4*)&bias[n0 + tx * 4];
    float4 bs1 = *(const float4*)&bias[n0 + 64 + tx * 4];
    #pragma unroll
    for (int r = 0; r < 4; r++) {
        int row = m0 + ty * 4 + r;
        float2 p0 = unpack2(acc[r][0]), p1 = unpack2(acc[r][1]);
        float2 p2 = unpack2(acc[r][2]), p3 = unpack2(acc[r][3]);
        float4 o0 = make_float4(p0.x + bs0.x, p0.y + bs0.y, p1.x + bs0.z, p1.y + bs0.w);
        float4 o1 = make_float4(p2.x + bs1.x, p2.y + bs1.y, p3.x + bs1.z, p3.y + bs1.w);
        *(float4*)&C[(size_t)row * ldc + n0 + tx * 4] = o0;
        *(float4*)&C[(size_t)row * ldc + n0 + 64 + tx * 4] = o1;
    }
}

// ---------------- fused QKV projection ----------------
// grid (10, 32): n-tiles 0..7 -> Q cols, 8 -> K, 9 -> V; m-tiles over 2048 rows.
__global__ void __launch_bounds__(256) qkv_kernel(
    const float* __restrict__ x,
    const float* __restrict__ Wq, const float* __restrict__ bq,
    const float* __restrict__ Wk, const float* __restrict__ bk,
    const float* __restrict__ Wv, const float* __restrict__ bv)
{
    const int nt = blockIdx.x, mt = blockIdx.y;
    const float *B, *bias; float* C; int ldb, ldc, n0;
    if (nt < 8)       { B = Wq; bias = bq; C = g_Q; ldb = DM; ldc = DM; n0 = nt * 128; }
    else if (nt == 8) { B = Wk; bias = bk; C = g_K; ldb = DV; ldc = DV; n0 = 0; }
    else              { B = Wv; bias = bv; C = g_V; ldb = DV; ldc = DV; n0 = 0; }
    sgemm_tile_64x128(x, DM, B, ldb, bias, C, ldc, mt * 64, n0, DM);
}

// ---------------- O projection ----------------
__global__ void __launch_bounds__(256) oproj_kernel(
    const float* __restrict__ Wo, const float* __restrict__ bo, float* __restrict__ out)
{
    sgemm_tile_64x128(g_O, DM, Wo, DM, bo, out, DM, blockIdx.y * 64, blockIdx.x * 128, DM);
}

// ---------------- flash attention ----------------
// CTA = (qb, h, b): 128 query rows, full 1024 keys in 8 blocks of 128.
// smem: Qt[d][i] (d-major), KPt[d][j] reused as Pt[j][i], Vs[j][dv].
#define QT_LD 132
#define ATTN_SMEM ((2 * 128 * QT_LD + 128 * DV) * 4)

__global__ void __launch_bounds__(256, 1) attn_kernel()
{
    extern __shared__ float sm[];
    float* Qt  = sm;                     // [128][132]
    float* KPt = sm + 128 * QT_LD;       // [128][132]  (K^T, then P^T)
    float* Vs  = sm + 2 * 128 * QT_LD;   // [128][128]

    const int tid = threadIdx.x;
    const int tx = tid & 15, ty = tid >> 4;
    const int qb = blockIdx.x, h = blockIdx.y, b = blockIdx.z;

    const float* Qg = g_Q + (size_t)b * (SEQ * DM) + h * (SEQ * DV) + qb * (128 * DV);
    const float* Kg = g_K + (size_t)b * (SEQ * DV);
    const float* Vg = g_V + (size_t)b * (SEQ * DV);
    float*       Og = g_O + (size_t)b * (SEQ * DM) + h * (SEQ * DV) + qb * (128 * DV);

    const int lr = tid >> 1;            // loader row 0..127
    const int lc = (tid & 1) * 64;      // loader column half

    // Q tile -> Qt transposed (once)
    #pragma unroll
    for (int u = 0; u < 16; u++) {
        int d = lc + u * 4;
        float4 v = *(const float4*)&Qg[lr * DV + d];
        Qt[(d + 0) * QT_LD + lr] = v.x;
        Qt[(d + 1) * QT_LD + lr] = v.y;
        Qt[(d + 2) * QT_LD + lr] = v.z;
        Qt[(d + 3) * QT_LD + lr] = v.w;
    }

    u64 oacc[8][4];
    #pragma unroll
    for (int r = 0; r < 8; r++)
        #pragma unroll
        for (int c = 0; c < 4; c++) oacc[r][c] = 0ull;
    float mrow[8], lrow[8];
    #pragma unroll
    for (int r = 0; r < 8; r++) { mrow[r] = -1e30f; lrow[r] = 0.f; }

    // 1/sqrt(128) * log2(e): softmax done in base-2 domain
    const float cscale = 0.08838834764831845f * 1.4426950408889634f;

    for (int kb = 0; kb < 8; kb++) {
        __syncthreads();   // protect KPt(P) + Vs of previous iteration
        const float* Kblk = Kg + kb * (128 * DV);
        const float* Vblk = Vg + kb * (128 * DV);
        #pragma unroll
        for (int u = 0; u < 16; u++) {
            int d = lc + u * 4;
            float4 kv = *(const float4*)&Kblk[lr * DV + d];
            KPt[(d + 0) * QT_LD + lr] = kv.x;
            KPt[(d + 1) * QT_LD + lr] = kv.y;
            KPt[(d + 2) * QT_LD + lr] = kv.z;
            KPt[(d + 3) * QT_LD + lr] = kv.w;
            *(float4*)&Vs[lr * DV + d] = *(const float4*)&Vblk[lr * DV + d];
        }
        __syncthreads();

        // S = Q K^T (128x128), 8x8 split-frag per thread
        u64 sacc[8][4];
        #pragma unroll
        for (int r = 0; r < 8; r++)
            #pragma unroll
            for (int c = 0; c < 4; c++) sacc[r][c] = 0ull;
        #pragma unroll 4
        for (int d = 0; d < 128; d++) {
            float a[8];
            *(float4*)&a[0] = *(const float4*)&Qt[d * QT_LD + ty * 4];
            *(float4*)&a[4] = *(const float4*)&Qt[d * QT_LD + 64 + ty * 4];
            ulonglong2 b0 = *(const ulonglong2*)&KPt[d * QT_LD + tx * 4];
            ulonglong2 b1 = *(const ulonglong2*)&KPt[d * QT_LD + 64 + tx * 4];
            #pragma unroll
            for (int r = 0; r < 8; r++) {
                u64 av = pack2(a[r]);
                ffma2(sacc[r][0], av, b0.x);
                ffma2(sacc[r][1], av, b0.y);
                ffma2(sacc[r][2], av, b1.x);
                ffma2(sacc[r][3], av, b1.y);
            }
        }

        // online softmax (rows shared by the 16 tx-lanes of one ty group)
        float p[8][8];
        #pragma unroll
        for (int r = 0; r < 8; r++) {
            float2 f0 = unpack2(sacc[r][0]);
            float2 f1 = unpack2(sacc[r][1]);
            float2 f2 = unpack2(sacc[r][2]);
            float2 f3 = unpack2(sacc[r][3]);
            float t[8] = {f0.x, f0.y, f1.x, f1.y, f2.x, f2.y, f3.x, f3.y};
            float rmax = -1e30f;
            #pragma unroll
            for (int j = 0; j < 8; j++) { t[j] *= cscale; rmax = fmaxf(rmax, t[j]); }
            #pragma unroll
            for (int off = 8; off >= 1; off >>= 1)
                rmax = fmaxf(rmax, __shfl_xor_sync(0xffffffffu, rmax, off));
            float mnew = fmaxf(mrow[r], rmax);
            float alpha = fast_exp2(mrow[r] - mnew);
            mrow[r] = mnew;
            float rsum = 0.f;
            #pragma unroll
            for (int j = 0; j < 8; j++) {
                float e = fast_exp2(t[j] - mnew);
                p[r][j] = e; rsum += e;
            }
            #pragma unroll
            for (int off = 8; off >= 1; off >>= 1)
                rsum += __shfl_xor_sync(0xffffffffu, rsum, off);
            lrow[r] = lrow[r] * alpha + rsum;
            u64 a2 = pack2(alpha);
            #pragma unroll
            for (int c = 0; c < 4; c++) fmul2(oacc[r][c], a2);
        }

        __syncthreads();   // everyone done reading KPt as K^T
        // P -> KPt as Pt[j][i]
        #pragma unroll
        for (int i = 0; i < 8; i++) {
            int row = (i < 4) ? (ty * 4 + i) : (64 + ty * 4 + (i - 4));
            #pragma unroll
            for (int j = 0; j < 8; j++) {
                int col = (j < 4) ? (tx * 4 + j) : (64 + tx * 4 + (j - 4));
                KPt[col * QT_LD + row] = p[i][j];
            }
        }
        __syncthreads();

        // O += P V
        #pragma unroll 4
        for (int j = 0; j < 128; j++) {
            float a[8];
            *(float4*)&a[0] = *(const float4*)&KPt[j * QT_LD + ty * 4];
            *(float4*)&a[4] = *(const float4*)&KPt[j * QT_LD + 64 + ty * 4];
            ulonglong2 b0 = *(const ulonglong2*)&Vs[j * DV + tx * 4];
            ulonglong2 b1 = *(const ulonglong2*)&Vs[j * DV + 64 + tx * 4];
            #pragma unroll
            for (int r = 0; r < 8; r++) {
                u64 av = pack2(a[r]);
                ffma2(oacc[r][0], av, b0.x);
                ffma2(oacc[r][1], av, b0.y);
                ffma2(oacc[r][2], av, b1.x);
                ffma2(oacc[r][3], av, b1.y);
            }
        }
    }

    // epilogue: O / l  -> g_O (flat (b,h,qi,d) == (b,s,dm) view)
    #pragma unroll
    for (int r = 0; r < 8; r++) {
        int row = (r < 4) ? (ty * 4 + r) : (64 + ty * 4 + (r - 4));
        float inv = 1.0f / lrow[r];
        float2 p0 = unpack2(oacc[r][0]), p1 = unpack2(oacc[r][1]);
        float2 p2 = unpack2(oacc[r][2]), p3 = unpack2(oacc[r][3]);
        float4 o0 = make_float4(p0.x * inv, p0.y * inv, p1.x * inv, p1.y * inv);
        float4 o1 = make_float4(p2.x * inv, p2.y * inv, p3.x * inv, p3.y * inv);
        *(float4*)&Og[row * DV + tx * 4] = o0;
        *(float4*)&Og[row * DV + 64 + tx * 4] = o1;
    }
}

// ---------------- launch ----------------
extern "C" void kernel_launch(void* const* d_in, const int* in_sizes, int n_in,
                              void* d_out, int out_size)
{
    const float* x  = (const float*)d_in[0];
    const float* Wq = (const float*)d_in[1];
    const float* bq = (const float*)d_in[2];
    const float* Wk = (const float*)d_in[3];
    const float* bk = (const float*)d_in[4];
    const float* Wv = (const float*)d_in[5];
    const float* bv = (const float*)d_in[6];
    const float* Wo = (const float*)d_in[7];
    const float* bo = (const float*)d_in[8];
    float* out = (float*)d_out;

    cudaFuncSetAttribute(attn_kernel, cudaFuncAttributeMaxDynamicSharedMemorySize, ATTN_SMEM);

    qkv_kernel<<<dim3(10, 32), 256>>>(x, Wq, bq, Wk, bk, Wv, bv);
    attn_kernel<<<dim3(SEQ / 128, HEADS, BATCH), 256, ATTN_SMEM>>>();
    oproj_kernel<<<dim3(DM / 128, (BATCH * SEQ) / 64), 256>>>(Wo, bo, out);
}

// round 3
// speedup vs baseline: 1.2722x; 1.2722x over previous
#include <cuda_runtime.h>
#include <cuda_bf16.h>
#include <cstdint>

#define BATCH 2
#define SEQ   1024
#define DM    1024
#define HEADS 8
#define DV    128

typedef unsigned long long u64;

// ======================= scratch (static device arrays) =======================
__device__ __nv_bfloat16 g_xhi[BATCH * SEQ * DM];
__device__ __nv_bfloat16 g_xlo[BATCH * SEQ * DM];
// W^T (K-major, rows = output features), stacked:
// [0,1024)=Wq^T  [1024,1152)=Wk^T  [1152,1280)=Wv^T  [1280,2304)=Wo^T
#define WT_ROWS 2304
__device__ __nv_bfloat16 g_WThi[WT_ROWS * DM];
__device__ __nv_bfloat16 g_WTlo[WT_ROWS * DM];
__device__ float g_Q[BATCH * SEQ * DM];
__device__ float g_K[BATCH * SEQ * DV];
__device__ float g_V[BATCH * SEQ * DV];
__device__ __nv_bfloat16 g_Ohi[BATCH * SEQ * DM];
__device__ __nv_bfloat16 g_Olo[BATCH * SEQ * DM];

// ======================= helpers =======================
__device__ __forceinline__ uint32_t smem_u32(const void* p) {
    uint32_t a;
    asm("{ .reg .u64 t; cvta.to.shared.u64 t, %1; cvt.u32.u64 %0, t; }" : "=r"(a) : "l"(p));
    return a;
}
// row-of-128B XOR swizzle (chunk ^= row&7); conflict-free STS + ldmatrix
#define SW128(off) ((off) ^ (((off) >> 3) & 0x70))

__device__ __forceinline__ void ldsm_x4(uint32_t addr, uint32_t* r) {
    asm volatile("ldmatrix.sync.aligned.m8n8.x4.shared.b16 {%0,%1,%2,%3}, [%4];"
        : "=r"(r[0]), "=r"(r[1]), "=r"(r[2]), "=r"(r[3]) : "r"(addr));
}
__device__ __forceinline__ void mma16816(float* d, const uint32_t* a, const uint32_t* b) {
    asm volatile("mma.sync.aligned.m16n8k16.row.col.f32.bf16.bf16.f32 "
        "{%0,%1,%2,%3}, {%4,%5,%6,%7}, {%8,%9}, {%0,%1,%2,%3};"
        : "+f"(d[0]), "+f"(d[1]), "+f"(d[2]), "+f"(d[3])
        : "r"(a[0]), "r"(a[1]), "r"(a[2]), "r"(a[3]), "r"(b[0]), "r"(b[1]));
}

// fp32 pair -> bf16 hi/lo split (packed bf16x2; lo lane = first element)
__device__ __forceinline__ void split2(float x, float y, uint32_t& h, uint32_t& l) {
    asm("cvt.rn.bf16x2.f32 %0, %1, %2;" : "=r"(h) : "f"(y), "f"(x));
    float hx = __uint_as_float(h << 16);
    float hy = __uint_as_float(h & 0xffff0000u);
    asm("cvt.rn.bf16x2.f32 %0, %1, %2;" : "=r"(l) : "f"(y - hy), "f"(x - hx));
}

// f32x2 helpers (attention)
__device__ __forceinline__ u64 pack2(float x) {
    u64 r; asm("mov.b64 %0, {%1, %1};" : "=l"(r) : "f"(x)); return r;
}
__device__ __forceinline__ void ffma2(u64& c, u64 a, u64 b) {
    asm("fma.rn.f32x2 %0, %1, %2, %0;" : "+l"(c) : "l"(a), "l"(b));
}
__device__ __forceinline__ void fmul2(u64& c, u64 a) {
    asm("mul.rn.f32x2 %0, %1, %0;" : "+l"(c) : "l"(a));
}
__device__ __forceinline__ float2 unpack2(u64 v) {
    float lo, hi; asm("mov.b64 {%0, %1}, %2;" : "=f"(lo), "=f"(hi) : "l"(v));
    return make_float2(lo, hi);
}
__device__ __forceinline__ float fast_exp2(float x) {
    float y; asm("ex2.approx.f32 %0, %1;" : "=f"(y) : "f"(x)); return y;
}

// ======================= prep: split x, transpose+split W =======================
__global__ void __launch_bounds__(256) prep_kernel(
    const float* __restrict__ x,  const float* __restrict__ Wq,
    const float* __restrict__ Wk, const float* __restrict__ Wv,
    const float* __restrict__ Wo)
{
    const int tid = threadIdx.x;
    const int bi = blockIdx.x;
    if (bi < 1024) {
        size_t base = (size_t)bi * 2048 + tid * 8;
        float4 a = *(const float4*)(x + base);
        float4 b = *(const float4*)(x + base + 4);
        uint32_t h0, l0, h1, l1, h2, l2, h3, l3;
        split2(a.x, a.y, h0, l0); split2(a.z, a.w, h1, l1);
        split2(b.x, b.y, h2, l2); split2(b.z, b.w, h3, l3);
        ((uint4*)g_xhi)[base >> 3] = make_uint4(h0, h1, h2, h3);
        ((uint4*)g_xlo)[base >> 3] = make_uint4(l0, l1, l2, l3);
        return;
    }
    int t = bi - 1024;
    const float* src; int N; int drow;
    if (t < 1024)      { src = Wq; N = 1024; drow = 0; }
    else if (t < 1152) { t -= 1024; src = Wk; N = 128;  drow = 1024; }
    else if (t < 1280) { t -= 1152; src = Wv; N = 128;  drow = 1152; }
    else               { t -= 1280; src = Wo; N = 1024; drow = 1280; }
    const int ntn = N >> 5;
    const int n0 = (t % ntn) * 32, k0 = (t / ntn) * 32;
    __shared__ float sm[32][33];
    const int tx = tid & 31, ty = tid >> 5;
    #pragma unroll
    for (int i = 0; i < 4; i++)
        sm[ty + 8 * i][tx] = src[(size_t)(k0 + ty + 8 * i) * N + n0 + tx];
    __syncthreads();
    #pragma unroll
    for (int i = 0; i < 4; i++) {
        int n = ty + 8 * i;
        float v = sm[tx][n];
        __nv_bfloat16 h = __float2bfloat16(v);
        size_t o = (size_t)(drow + n0 + n) * DM + k0 + tx;
        g_WThi[o] = h;
        g_WTlo[o] = __float2bfloat16(v - __bfloat162float(h));
    }
}

// ======================= mma.sync bf16-split GEMM =======================
// CTA tile 128x128, K=1024 in 16 chunks of 64. Single-stage smem, 2 CTA/SM.
// smem regions (each 128 rows x 128B, swizzled): Ahi Alo Bhi Blo.
#define G_REG  16384
#define G_SMEM (4 * G_REG)

__global__ void __launch_bounds__(256, 2) gemm_kernel(
    const __nv_bfloat16* __restrict__ Ahi, const __nv_bfloat16* __restrict__ Alo,
    const float* __restrict__ bq, const float* __restrict__ bk,
    const float* __restrict__ bv, const float* __restrict__ bo,
    float* __restrict__ dout, int mode)
{
    extern __shared__ char smem[];
    const uint32_t sb = smem_u32(smem);
    const int tid = threadIdx.x;
    const int wid = tid >> 5, lane = tid & 31;

    const int nt_blk = blockIdx.x;
    const int m0 = blockIdx.y * 128;

    int wrow, n0, ldc; const float* bias; float* C;
    if (mode == 0) {
        if (nt_blk < 8)       { wrow = nt_blk * 128; C = g_Q; ldc = DM; n0 = nt_blk * 128; bias = bq; }
        else if (nt_blk == 8) { wrow = 1024;         C = g_K; ldc = DV; n0 = 0;            bias = bk; }
        else                  { wrow = 1152;         C = g_V; ldc = DV; n0 = 0;            bias = bv; }
    } else {
        wrow = 1280 + nt_blk * 128; C = dout; ldc = DM; n0 = nt_blk * 128; bias = bo;
    }

    // loader geometry: per thread 4 x 16B per region per chunk
    const int rowA = tid >> 1;
    const int e0 = (tid & 1) * 32;
    uint32_t swo[4];
    #pragma unroll
    for (int i = 0; i < 4; i++)
        swo[i] = SW128((uint32_t)(rowA * 128 + (e0 + i * 8) * 2));
    const size_t aRowOff = (size_t)(m0 + rowA) * DM + e0;
    const size_t bRowOff = (size_t)(wrow + rowA) * DM + e0;

    // warp tiling: 4 (m) x 2 (n); warp tile 32 x 64
    const int wm = wid >> 1, wn = wid & 1;
    const int mbase = wm * 32, nbase = wn * 64;

    float acc[2][8][4];
    #pragma unroll
    for (int mt = 0; mt < 2; mt++)
        #pragma unroll
        for (int nt = 0; nt < 8; nt++)
            #pragma unroll
            for (int j = 0; j < 4; j++) acc[mt][nt][j] = 0.f;

    // ldmatrix lane addressing (bytes within a region)
    const int arow = (lane & 7) + ((lane >> 3) & 1) * 8;          // + mbase + mt*16
    const int akc  = (lane >> 4) & 1;                             // k-chunk add (8 elems)
    const int brow = (lane & 7) + ((lane >> 4) & 1) * 8;          // + nbase + nq*16
    const int bkc  = (lane >> 3) & 1;

    #pragma unroll 1
    for (int kt = 0; kt < 16; kt++) {
        const int k0 = kt * 64;
        __syncthreads();   // previous compute done reading smem
        #pragma unroll
        for (int i = 0; i < 4; i++) {
            uint4 v;
            v = *(const uint4*)(Ahi + aRowOff + k0 + i * 8);
            *(uint4*)(smem + 0 * G_REG + swo[i]) = v;
            v = *(const uint4*)(Alo + aRowOff + k0 + i * 8);
            *(uint4*)(smem + 1 * G_REG + swo[i]) = v;
            v = *(const uint4*)(g_WThi + bRowOff + k0 + i * 8);
            *(uint4*)(smem + 2 * G_REG + swo[i]) = v;
            v = *(const uint4*)(g_WTlo + bRowOff + k0 + i * 8);
            *(uint4*)(smem + 3 * G_REG + swo[i]) = v;
        }
        __syncthreads();

        #pragma unroll
        for (int ks = 0; ks < 4; ks++) {
            uint32_t ah[2][4], al[2][4], bh[4][4], bl[4][4];
            #pragma unroll
            for (int mt = 0; mt < 2; mt++) {
                int r = mbase + mt * 16 + arow;
                int ke = ks * 16 + akc * 8;
                uint32_t off = (uint32_t)(r * 128 + (((ke >> 3) ^ (r & 7)) << 4));
                ldsm_x4(sb + 0 * G_REG + off, ah[mt]);
                ldsm_x4(sb + 1 * G_REG + off, al[mt]);
            }
            #pragma unroll
            for (int nq = 0; nq < 4; nq++) {
                int r = nbase + nq * 16 + brow;
                int ke = ks * 16 + bkc * 8;
                uint32_t off = (uint32_t)(r * 128 + (((ke >> 3) ^ (r & 7)) << 4));
                ldsm_x4(sb + 2 * G_REG + off, bh[nq]);
                ldsm_x4(sb + 3 * G_REG + off, bl[nq]);
            }
            #pragma unroll
            for (int mt = 0; mt < 2; mt++)
                #pragma unroll
                for (int nt = 0; nt < 8; nt++) {
                    const uint32_t* bhp = &bh[nt >> 1][(nt & 1) * 2];
                    const uint32_t* blp = &bl[nt >> 1][(nt & 1) * 2];
                    mma16816(acc[mt][nt], ah[mt], bhp);
                    mma16816(acc[mt][nt], ah[mt], blp);
                    mma16816(acc[mt][nt], al[mt], bhp);
                }
        }
    }

    // epilogue
    const int qrow = lane >> 2, qcol = (lane & 3) * 2;
    #pragma unroll
    for (int mt = 0; mt < 2; mt++) {
        #pragma unroll
        for (int nt = 0; nt < 8; nt++) {
            int c = nbase + nt * 8 + qcol;
            float b0 = bias[n0 + c], b1 = bias[n0 + c + 1];
            int r0 = m0 + mbase + mt * 16 + qrow;
            *(float2*)&C[(size_t)r0 * ldc + n0 + c] =
                make_float2(acc[mt][nt][0] + b0, acc[mt][nt][1] + b1);
            *(float2*)&C[(size_t)(r0 + 8) * ldc + n0 + c] =
                make_float2(acc[mt][nt][2] + b0, acc[mt][nt][3] + b1);
        }
    }
}

// ======================= flash attention (SIMT, verified core) =======================
#define QT_LD 132
#define ATTN_SMEM ((2 * 128 * QT_LD + 128 * DV) * 4)

__global__ void __launch_bounds__(256, 1) attn_kernel()
{
    extern __shared__ float sm[];
    float* Qt  = sm;
    float* KPt = sm + 128 * QT_LD;
    float* Vs  = sm + 2 * 128 * QT_LD;

    const int tid = threadIdx.x;
    const int tx = tid & 15, ty = tid >> 4;
    const int qb = blockIdx.x, h = blockIdx.y, b = blockIdx.z;

    const float* Qg = g_Q + (size_t)b * (SEQ * DM) + h * (SEQ * DV) + qb * (128 * DV);
    const float* Kg = g_K + (size_t)b * (SEQ * DV);
    const float* Vg = g_V + (size_t)b * (SEQ * DV);
    __nv_bfloat16* OgH = g_Ohi + (size_t)b * (SEQ * DM) + h * (SEQ * DV) + qb * (128 * DV);
    __nv_bfloat16* OgL = g_Olo + (size_t)b * (SEQ * DM) + h * (SEQ * DV) + qb * (128 * DV);

    const int lr = tid >> 1;
    const int lc = (tid & 1) * 64;

    #pragma unroll
    for (int u = 0; u < 16; u++) {
        int d = lc + u * 4;
        float4 v = *(const float4*)&Qg[lr * DV + d];
        Qt[(d + 0) * QT_LD + lr] = v.x;
        Qt[(d + 1) * QT_LD + lr] = v.y;
        Qt[(d + 2) * QT_LD + lr] = v.z;
        Qt[(d + 3) * QT_LD + lr] = v.w;
    }

    u64 oacc[8][4];
    #pragma unroll
    for (int r = 0; r < 8; r++)
        #pragma unroll
        for (int c = 0; c < 4; c++) oacc[r][c] = 0ull;
    float mrow[8], lrow[8];
    #pragma unroll
    for (int r = 0; r < 8; r++) { mrow[r] = -1e30f; lrow[r] = 0.f; }

    const float cscale = 0.08838834764831845f * 1.4426950408889634f;

    for (int kb = 0; kb < 8; kb++) {
        __syncthreads();
        const float* Kblk = Kg + kb * (128 * DV);
        const float* Vblk = Vg + kb * (128 * DV);
        #pragma unroll
        for (int u = 0; u < 16; u++) {
            int d = lc + u * 4;
            float4 kv = *(const float4*)&Kblk[lr * DV + d];
            KPt[(d + 0) * QT_LD + lr] = kv.x;
            KPt[(d + 1) * QT_LD + lr] = kv.y;
            KPt[(d + 2) * QT_LD + lr] = kv.z;
            KPt[(d + 3) * QT_LD + lr] = kv.w;
            *(float4*)&Vs[lr * DV + d] = *(const float4*)&Vblk[lr * DV + d];
        }
        __syncthreads();

        u64 sacc[8][4];
        #pragma unroll
        for (int r = 0; r < 8; r++)
            #pragma unroll
            for (int c = 0; c < 4; c++) sacc[r][c] = 0ull;
        #pragma unroll 4
        for (int d = 0; d < 128; d++) {
            float a[8];
            *(float4*)&a[0] = *(const float4*)&Qt[d * QT_LD + ty * 4];
            *(float4*)&a[4] = *(const float4*)&Qt[d * QT_LD + 64 + ty * 4];
            ulonglong2 b0 = *(const ulonglong2*)&KPt[d * QT_LD + tx * 4];
            ulonglong2 b1 = *(const ulonglong2*)&KPt[d * QT_LD + 64 + tx * 4];
            #pragma unroll
            for (int r = 0; r < 8; r++) {
                u64 av = pack2(a[r]);
                ffma2(sacc[r][0], av, b0.x);
                ffma2(sacc[r][1], av, b0.y);
                ffma2(sacc[r][2], av, b1.x);
                ffma2(sacc[r][3], av, b1.y);
            }
        }

        float p[8][8];
        #pragma unroll
        for (int r = 0; r < 8; r++) {
            float2 f0 = unpack2(sacc[r][0]);
            float2 f1 = unpack2(sacc[r][1]);
            float2 f2 = unpack2(sacc[r][2]);
            float2 f3 = unpack2(sacc[r][3]);
            float t[8] = {f0.x, f0.y, f1.x, f1.y, f2.x, f2.y, f3.x, f3.y};
            float rmax = -1e30f;
            #pragma unroll
            for (int j = 0; j < 8; j++) { t[j] *= cscale; rmax = fmaxf(rmax, t[j]); }
            #pragma unroll
            for (int off = 8; off >= 1; off >>= 1)
                rmax = fmaxf(rmax, __shfl_xor_sync(0xffffffffu, rmax, off));
            float mnew = fmaxf(mrow[r], rmax);
            float alpha = fast_exp2(mrow[r] - mnew);
            mrow[r] = mnew;
            float rsum = 0.f;
            #pragma unroll
            for (int j = 0; j < 8; j++) {
                float e = fast_exp2(t[j] - mnew);
                p[r][j] = e; rsum += e;
            }
            #pragma unroll
            for (int off = 8; off >= 1; off >>= 1)
                rsum += __shfl_xor_sync(0xffffffffu, rsum, off);
            lrow[r] = lrow[r] * alpha + rsum;
            u64 a2 = pack2(alpha);
            #pragma unroll
            for (int c = 0; c < 4; c++) fmul2(oacc[r][c], a2);
        }

        __syncthreads();
        #pragma unroll
        for (int i = 0; i < 8; i++) {
            int row = (i < 4) ? (ty * 4 + i) : (64 + ty * 4 + (i - 4));
            #pragma unroll
            for (int j = 0; j < 8; j++) {
                int col = (j < 4) ? (tx * 4 + j) : (64 + tx * 4 + (j - 4));
                KPt[col * QT_LD + row] = p[i][j];
            }
        }
        __syncthreads();

        #pragma unroll 4
        for (int j = 0; j < 128; j++) {
            float a[8];
            *(float4*)&a[0] = *(const float4*)&KPt[j * QT_LD + ty * 4];
            *(float4*)&a[4] = *(const float4*)&KPt[j * QT_LD + 64 + ty * 4];
            ulonglong2 b0 = *(const ulonglong2*)&Vs[j * DV + tx * 4];
            ulonglong2 b1 = *(const ulonglong2*)&Vs[j * DV + 64 + tx * 4];
            #pragma unroll
            for (int r = 0; r < 8; r++) {
                u64 av = pack2(a[r]);
                ffma2(oacc[r][0], av, b0.x);
                ffma2(oacc[r][1], av, b0.y);
                ffma2(oacc[r][2], av, b1.x);
                ffma2(oacc[r][3], av, b1.y);
            }
        }
    }

    #pragma unroll
    for (int r = 0; r < 8; r++) {
        int row = (r < 4) ? (ty * 4 + r) : (64 + ty * 4 + (r - 4));
        float inv = 1.0f / lrow[r];
        float2 p0 = unpack2(oacc[r][0]), p1 = unpack2(oacc[r][1]);
        float2 p2 = unpack2(oacc[r][2]), p3 = unpack2(oacc[r][3]);
        uint32_t h01, l01, h23, l23, h45, l45, h67, l67;
        split2(p0.x * inv, p0.y * inv, h01, l01);
        split2(p1.x * inv, p1.y * inv, h23, l23);
        split2(p2.x * inv, p2.y * inv, h45, l45);
        split2(p3.x * inv, p3.y * inv, h67, l67);
        size_t off0 = (size_t)row * DV + tx * 4;
        *(uint2*)((char*)OgH + off0 * 2) = make_uint2(h01, h23);
        *(uint2*)((char*)OgL + off0 * 2) = make_uint2(l01, l23);
        size_t off1 = off0 + 64;
        *(uint2*)((char*)OgH + off1 * 2) = make_uint2(h45, h67);
        *(uint2*)((char*)OgL + off1 * 2) = make_uint2(l45, l67);
    }
}

// ======================= launch =======================
extern "C" void kernel_launch(void* const* d_in, const int* in_sizes, int n_in,
                              void* d_out, int out_size)
{
    const float* x  = (const float*)d_in[0];
    const float* Wq = (const float*)d_in[1];
    const float* bq = (const float*)d_in[2];
    const float* Wk = (const float*)d_in[3];
    const float* bk = (const float*)d_in[4];
    const float* Wv = (const float*)d_in[5];
    const float* bv = (const float*)d_in[6];
    const float* Wo = (const float*)d_in[7];
    const float* bo = (const float*)d_in[8];
    float* out = (float*)d_out;

    cudaFuncSetAttribute(attn_kernel, cudaFuncAttributeMaxDynamicSharedMemorySize, ATTN_SMEM);
    cudaFuncSetAttribute(gemm_kernel, cudaFuncAttributeMaxDynamicSharedMemorySize, G_SMEM);

    __nv_bfloat16 *xhi, *xlo, *ohi, *olo;
    cudaGetSymbolAddress((void**)&xhi, g_xhi);
    cudaGetSymbolAddress((void**)&xlo, g_xlo);
    cudaGetSymbolAddress((void**)&ohi, g_Ohi);
    cudaGetSymbolAddress((void**)&olo, g_Olo);

    prep_kernel<<<3328, 256>>>(x, Wq, Wk, Wv, Wo);
    gemm_kernel<<<dim3(10, 16), 256, G_SMEM>>>(xhi, xlo, bq, bk, bv, bo, out, 0);
    attn_kernel<<<dim3(SEQ / 128, HEADS, BATCH), 256, ATTN_SMEM>>>();
    gemm_kernel<<<dim3(8, 16), 256, G_SMEM>>>(ohi, olo, bq, bk, bv, bo, out, 1);
}

// round 4
// speedup vs baseline: 2.3224x; 1.8255x over previous
#include <cuda_runtime.h>
#include <cuda_bf16.h>
#include <cstdint>

#define BATCH 2
#define SEQ   1024
#define DM    1024
#define HEADS 8
#define DV    128

// ======================= scratch (static device arrays) =======================
__device__ __nv_bfloat16 g_xhi[BATCH * SEQ * DM];
__device__ __nv_bfloat16 g_xlo[BATCH * SEQ * DM];
// W^T (K-major): [0,1024)=Wq^T  [1024,1152)=Wk^T  [1152,1280)=Wv^T  [1280,2304)=Wo^T
#define WT_ROWS 2304
__device__ __nv_bfloat16 g_WThi[WT_ROWS * DM];
__device__ __nv_bfloat16 g_WTlo[WT_ROWS * DM];
// attention operands (bf16 hi/lo), flat-view layouts:
__device__ __nv_bfloat16 g_Qhi[BATCH * SEQ * DM];   // (b,s,dm) flat == per-head slabs
__device__ __nv_bfloat16 g_Qlo[BATCH * SEQ * DM];
__device__ __nv_bfloat16 g_Khi[BATCH * SEQ * DV];   // [b][key][dv]
__device__ __nv_bfloat16 g_Klo[BATCH * SEQ * DV];
__device__ __nv_bfloat16 g_Vthi[BATCH * DV * SEQ];  // [b][dv][key]  (transposed)
__device__ __nv_bfloat16 g_Vtlo[BATCH * DV * SEQ];
__device__ __nv_bfloat16 g_Ohi[BATCH * SEQ * DM];
__device__ __nv_bfloat16 g_Olo[BATCH * SEQ * DM];

// ======================= helpers =======================
__device__ __forceinline__ uint32_t smem_u32(const void* p) {
    uint32_t a;
    asm("{ .reg .u64 t; cvta.to.shared.u64 t, %1; cvt.u32.u64 %0, t; }" : "=r"(a) : "l"(p));
    return a;
}
// swizzles: rows of 128B / 256B
#define SW128(off) ((off) ^ (((off) >> 3) & 0x70))
#define SW256(off) ((off) ^ (((off) >> 4) & 0x70))

__device__ __forceinline__ void ldsm_x4(uint32_t addr, uint32_t* r) {
    asm volatile("ldmatrix.sync.aligned.m8n8.x4.shared.b16 {%0,%1,%2,%3}, [%4];"
        : "=r"(r[0]), "=r"(r[1]), "=r"(r[2]), "=r"(r[3]) : "r"(addr));
}
__device__ __forceinline__ void mma16816(float* d, const uint32_t* a, const uint32_t* b) {
    asm volatile("mma.sync.aligned.m16n8k16.row.col.f32.bf16.bf16.f32 "
        "{%0,%1,%2,%3}, {%4,%5,%6,%7}, {%8,%9}, {%0,%1,%2,%3};"
        : "+f"(d[0]), "+f"(d[1]), "+f"(d[2]), "+f"(d[3])
        : "r"(a[0]), "r"(a[1]), "r"(a[2]), "r"(a[3]), "r"(b[0]), "r"(b[1]));
}
__device__ __forceinline__ void cpasync16(uint32_t dst, const void* src) {
    asm volatile("cp.async.cg.shared.global [%0], [%1], 16;" :: "r"(dst), "l"(src));
}
#define CP_COMMIT() asm volatile("cp.async.commit_group;" ::: "memory")
#define CP_WAIT0()  asm volatile("cp.async.wait_group 0;" ::: "memory")
#define CP_WAIT1()  asm volatile("cp.async.wait_group 1;" ::: "memory")

// fp32 pair -> bf16 hi/lo split (packed bf16x2; lo lane = first element)
__device__ __forceinline__ void split2(float x, float y, uint32_t& h, uint32_t& l) {
    asm("cvt.rn.bf16x2.f32 %0, %1, %2;" : "=r"(h) : "f"(y), "f"(x));
    float hx = __uint_as_float(h << 16);
    float hy = __uint_as_float(h & 0xffff0000u);
    asm("cvt.rn.bf16x2.f32 %0, %1, %2;" : "=r"(l) : "f"(y - hy), "f"(x - hx));
}
__device__ __forceinline__ float fast_exp2(float x) {
    float y; asm("ex2.approx.f32 %0, %1;" : "=f"(y) : "f"(x)); return y;
}

// ======================= prep: split x, transpose+split W =======================
__global__ void __launch_bounds__(256) prep_kernel(
    const float* __restrict__ x,  const float* __restrict__ Wq,
    const float* __restrict__ Wk, const float* __restrict__ Wv,
    const float* __restrict__ Wo)
{
    const int tid = threadIdx.x;
    const int bi = blockIdx.x;
    if (bi < 1024) {
        size_t base = (size_t)bi * 2048 + tid * 8;
        float4 a = *(const float4*)(x + base);
        float4 b = *(const float4*)(x + base + 4);
        uint32_t h0, l0, h1, l1, h2, l2, h3, l3;
        split2(a.x, a.y, h0, l0); split2(a.z, a.w, h1, l1);
        split2(b.x, b.y, h2, l2); split2(b.z, b.w, h3, l3);
        ((uint4*)g_xhi)[base >> 3] = make_uint4(h0, h1, h2, h3);
        ((uint4*)g_xlo)[base >> 3] = make_uint4(l0, l1, l2, l3);
        return;
    }
    int t = bi - 1024;
    const float* src; int N; int drow;
    if (t < 1024)      { src = Wq; N = 1024; drow = 0; }
    else if (t < 1152) { t -= 1024; src = Wk; N = 128;  drow = 1024; }
    else if (t < 1280) { t -= 1152; src = Wv; N = 128;  drow = 1152; }
    else               { t -= 1280; src = Wo; N = 1024; drow = 1280; }
    const int ntn = N >> 5;
    const int n0 = (t % ntn) * 32, k0 = (t / ntn) * 32;
    __shared__ float sm[32][33];
    const int tx = tid & 31, ty = tid >> 5;
    #pragma unroll
    for (int i = 0; i < 4; i++)
        sm[ty + 8 * i][tx] = src[(size_t)(k0 + ty + 8 * i) * N + n0 + tx];
    __syncthreads();
    #pragma unroll
    for (int i = 0; i < 4; i++) {
        int n = ty + 8 * i;
        float v = sm[tx][n];
        __nv_bfloat16 h = __float2bfloat16(v);
        size_t o = (size_t)(drow + n0 + n) * DM + k0 + tx;
        g_WThi[o] = h;
        g_WTlo[o] = __float2bfloat16(v - __bfloat162float(h));
    }
}

// ======================= mma.sync bf16-split GEMM (cp.async 2-stage) =======================
// CTA tile 128x128, K=1024 in 16 chunks of 64. Two smem stages of 4 regions
// (Ahi Alo Bhi Blo, each 128 rows x 128B SW128).
#define G_REG   16384
#define G_STAGE (4 * G_REG)
#define G_SMEM  (2 * G_STAGE)

__global__ void __launch_bounds__(256, 1) gemm_kernel(
    const __nv_bfloat16* __restrict__ Ahi, const __nv_bfloat16* __restrict__ Alo,
    const float* __restrict__ bq, const float* __restrict__ bk,
    const float* __restrict__ bv, const float* __restrict__ bo,
    float* __restrict__ dout, int mode)
{
    extern __shared__ char smem[];
    const uint32_t sb = smem_u32(smem);
    const int tid = threadIdx.x;
    const int wid = tid >> 5, lane = tid & 31;

    const int nt_blk = blockIdx.x;
    const int m0 = blockIdx.y * 128;

    int wrow, n0; const float* bias;
    if (mode == 0) {
        if (nt_blk < 8)       { wrow = nt_blk * 128; n0 = nt_blk * 128; bias = bq; }
        else if (nt_blk == 8) { wrow = 1024;         n0 = 0;            bias = bk; }
        else                  { wrow = 1152;         n0 = 0;            bias = bv; }
    } else {
        wrow = 1280 + nt_blk * 128; n0 = nt_blk * 128; bias = bo;
    }

    // loader geometry: per thread 4 x 16B per region per chunk
    const int rowA = tid >> 1;
    const int e0 = (tid & 1) * 32;
    uint32_t swo[4];
    #pragma unroll
    for (int i = 0; i < 4; i++)
        swo[i] = SW128((uint32_t)(rowA * 128 + (e0 + i * 8) * 2));
    const size_t aRowOff = (size_t)(m0 + rowA) * DM + e0;
    const size_t bRowOff = (size_t)(wrow + rowA) * DM + e0;

    // warp tiling: 4 (m) x 2 (n); warp tile 32 x 64
    const int wm = wid >> 1, wn = wid & 1;
    const int mbase = wm * 32, nbase = wn * 64;

    float acc[2][8][4];
    #pragma unroll
    for (int mt = 0; mt < 2; mt++)
        #pragma unroll
        for (int nt = 0; nt < 8; nt++)
            #pragma unroll
            for (int j = 0; j < 4; j++) acc[mt][nt][j] = 0.f;

    const int arow = (lane & 7) + ((lane >> 3) & 1) * 8;
    const int akc  = (lane >> 4) & 1;
    const int brow = (lane & 7) + ((lane >> 4) & 1) * 8;
    const int bkc  = (lane >> 3) & 1;

    // --- issue stage helper (inline) ---
    #define G_ISSUE(kt_) do { \
        const uint32_t base_ = sb + ((kt_) & 1) * G_STAGE; \
        const int k0_ = (kt_) * 64; \
        _Pragma("unroll") \
        for (int i = 0; i < 4; i++) { \
            cpasync16(base_ + 0 * G_REG + swo[i], Ahi + aRowOff + k0_ + i * 8); \
            cpasync16(base_ + 1 * G_REG + swo[i], Alo + aRowOff + k0_ + i * 8); \
            cpasync16(base_ + 2 * G_REG + swo[i], g_WThi + bRowOff + k0_ + i * 8); \
            cpasync16(base_ + 3 * G_REG + swo[i], g_WTlo + bRowOff + k0_ + i * 8); \
        } \
        CP_COMMIT(); \
    } while (0)

    G_ISSUE(0);

    #pragma unroll 1
    for (int kt = 0; kt < 16; kt++) {
        if (kt < 15) { G_ISSUE(kt + 1); CP_WAIT1(); }
        else         { CP_WAIT0(); }
        __syncthreads();
        const uint32_t rb = sb + (kt & 1) * G_STAGE;

        #pragma unroll
        for (int ks = 0; ks < 4; ks++) {
            uint32_t ah[2][4], al[2][4], bh[4][4], bl[4][4];
            #pragma unroll
            for (int mt = 0; mt < 2; mt++) {
                int r = mbase + mt * 16 + arow;
                int ke = ks * 16 + akc * 8;
                uint32_t off = (uint32_t)(r * 128 + (((ke >> 3) ^ (r & 7)) << 4));
                ldsm_x4(rb + 0 * G_REG + off, ah[mt]);
                ldsm_x4(rb + 1 * G_REG + off, al[mt]);
            }
            #pragma unroll
            for (int nq = 0; nq < 4; nq++) {
                int r = nbase + nq * 16 + brow;
                int ke = ks * 16 + bkc * 8;
                uint32_t off = (uint32_t)(r * 128 + (((ke >> 3) ^ (r & 7)) << 4));
                ldsm_x4(rb + 2 * G_REG + off, bh[nq]);
                ldsm_x4(rb + 3 * G_REG + off, bl[nq]);
            }
            #pragma unroll
            for (int mt = 0; mt < 2; mt++)
                #pragma unroll
                for (int nt = 0; nt < 8; nt++) {
                    const uint32_t* bhp = &bh[nt >> 1][(nt & 1) * 2];
                    const uint32_t* blp = &bl[nt >> 1][(nt & 1) * 2];
                    mma16816(acc[mt][nt], ah[mt], bhp);
                    mma16816(acc[mt][nt], ah[mt], blp);
                    mma16816(acc[mt][nt], al[mt], bhp);
                }
        }
        __syncthreads();
    }
    #undef G_ISSUE

    // ---------------- epilogue ----------------
    const int qrow = lane >> 2, qcol = (lane & 3) * 2;
    #pragma unroll
    for (int mt = 0; mt < 2; mt++) {
        #pragma unroll
        for (int nt = 0; nt < 8; nt++) {
            int c = nbase + nt * 8 + qcol;
            float b0 = bias[n0 + c], b1 = bias[n0 + c + 1];
            int r0 = m0 + mbase + mt * 16 + qrow;
            float v0 = acc[mt][nt][0] + b0, v1 = acc[mt][nt][1] + b1;
            float v2 = acc[mt][nt][2] + b0, v3 = acc[mt][nt][3] + b1;
            if (mode == 1) {
                *(float2*)&dout[(size_t)r0 * DM + n0 + c] = make_float2(v0, v1);
                *(float2*)&dout[(size_t)(r0 + 8) * DM + n0 + c] = make_float2(v2, v3);
            } else if (nt_blk < 8) {           // Q -> bf16 hi/lo, (b,s,dm) flat
                uint32_t h, l;
                split2(v0, v1, h, l);
                *(uint32_t*)((__nv_bfloat16*)g_Qhi + (size_t)r0 * DM + n0 + c) = h;
                *(uint32_t*)((__nv_bfloat16*)g_Qlo + (size_t)r0 * DM + n0 + c) = l;
                split2(v2, v3, h, l);
                *(uint32_t*)((__nv_bfloat16*)g_Qhi + (size_t)(r0 + 8) * DM + n0 + c) = h;
                *(uint32_t*)((__nv_bfloat16*)g_Qlo + (size_t)(r0 + 8) * DM + n0 + c) = l;
            } else if (nt_blk == 8) {          // K -> bf16 hi/lo, [b][key][dv]
                uint32_t h, l;
                split2(v0, v1, h, l);
                *(uint32_t*)((__nv_bfloat16*)g_Khi + (size_t)r0 * DV + c) = h;
                *(uint32_t*)((__nv_bfloat16*)g_Klo + (size_t)r0 * DV + c) = l;
                split2(v2, v3, h, l);
                *(uint32_t*)((__nv_bfloat16*)g_Khi + (size_t)(r0 + 8) * DV + c) = h;
                *(uint32_t*)((__nv_bfloat16*)g_Klo + (size_t)(r0 + 8) * DV + c) = l;
            } else {                           // V -> transposed bf16 hi/lo [b][dv][key]
                float vals[4] = {v0, v1, v2, v3};
                #pragma unroll
                for (int j = 0; j < 4; j++) {
                    int row = r0 + (j >> 1) * 8;
                    int col = c + (j & 1);
                    int bb = row >> 10, key = row & 1023;
                    size_t o = (size_t)bb * (DV * SEQ) + (size_t)col * SEQ + key;
                    __nv_bfloat16 hh = __float2bfloat16(vals[j]);
                    g_Vthi[o] = hh;
                    g_Vtlo[o] = __float2bfloat16(vals[j] - __bfloat162float(hh));
                }
            }
        }
    }
}

// ======================= flash attention (mma.sync bf16-split) =======================
// CTA = (qb,h,b): 128 q-rows x 1024 keys; 8 warps, warp = 16 q-rows.
// smem: Qhi/Qlo [128 q][128 dv] (SW256), 2 stages x { Khi/Klo [64 key][128 dv] SW256,
//                                                     Vthi/Vtlo [128 dv][64 key] SW128 }.
#define AQ_HI  0
#define AQ_LO  32768
#define AST0   65536
#define AK_HI  0
#define AK_LO  16384
#define AV_HI  32768
#define AV_LO  49152
#define ASTAGE 65536
#define ATTN_SMEM (AST0 + 2 * ASTAGE)   // 196608

__global__ void __launch_bounds__(256, 1) attn_kernel()
{
    extern __shared__ char smem[];
    const uint32_t sb = smem_u32(smem);
    const int tid = threadIdx.x;
    const int wid = tid >> 5, lane = tid & 31;
    const int qb = blockIdx.x, h = blockIdx.y, b = blockIdx.z;

    const __nv_bfloat16* Qh = g_Qhi + (size_t)b * (SEQ * DM) + h * (SEQ * DV) + qb * (128 * DV);
    const __nv_bfloat16* Ql = g_Qlo + (size_t)b * (SEQ * DM) + h * (SEQ * DV) + qb * (128 * DV);
    const __nv_bfloat16* Kh = g_Khi + (size_t)b * (SEQ * DV);
    const __nv_bfloat16* Kl = g_Klo + (size_t)b * (SEQ * DV);
    const __nv_bfloat16* Vh = g_Vthi + (size_t)b * (DV * SEQ);
    const __nv_bfloat16* Vl = g_Vtlo + (size_t)b * (DV * SEQ);
    __nv_bfloat16* OgH = g_Ohi + (size_t)b * (SEQ * DM) + h * (SEQ * DV) + qb * (128 * DV);
    __nv_bfloat16* OgL = g_Olo + (size_t)b * (SEQ * DM) + h * (SEQ * DV) + qb * (128 * DV);

    // ---- Q load (group 0, together with stage 0) ----
    #pragma unroll
    for (int i = 0; i < 8; i++) {
        int id = tid + i * 256;
        int row = id >> 4, kc = id & 15;
        uint32_t d = SW256((uint32_t)(row * 256 + kc * 16));
        cpasync16(sb + AQ_HI + d, Qh + row * 128 + kc * 8);
        cpasync16(sb + AQ_LO + d, Ql + row * 128 + kc * 8);
    }
    #define A_ISSUE(s_) do { \
        const uint32_t base_ = sb + AST0 + ((s_) & 1) * ASTAGE; \
        const int k0_ = (s_) * 64; \
        _Pragma("unroll") \
        for (int i = 0; i < 4; i++) { \
            int id = tid + i * 256; \
            int kr = id >> 4, kcc = id & 15; \
            uint32_t dk = SW256((uint32_t)(kr * 256 + kcc * 16)); \
            cpasync16(base_ + AK_HI + dk, Kh + (size_t)(k0_ + kr) * 128 + kcc * 8); \
            cpasync16(base_ + AK_LO + dk, Kl + (size_t)(k0_ + kr) * 128 + kcc * 8); \
            int vr = id >> 3, vc = id & 7; \
            uint32_t dv_ = SW128((uint32_t)(vr * 128 + vc * 16)); \
            cpasync16(base_ + AV_HI + dv_, Vh + (size_t)vr * 1024 + k0_ + vc * 8); \
            cpasync16(base_ + AV_LO + dv_, Vl + (size_t)vr * 1024 + k0_ + vc * 8); \
        } \
        CP_COMMIT(); \
    } while (0)

    A_ISSUE(0);   // commits group containing Q + stage 0

    const int mbase = wid * 16;
    const int arow = (lane & 7) + ((lane >> 3) & 1) * 8;
    const int akc  = (lane >> 4) & 1;
    const int brow = (lane & 7) + ((lane >> 4) & 1) * 8;
    const int bkc  = (lane >> 3) & 1;

    float oacc[16][4];
    #pragma unroll
    for (int i = 0; i < 16; i++)
        #pragma unroll
        for (int j = 0; j < 4; j++) oacc[i][j] = 0.f;
    float m0r = -1e30f, m1r = -1e30f, l0r = 0.f, l1r = 0.f;

    const float cscale = 0.08838834764831845f * 1.4426950408889634f;

    #pragma unroll 1
    for (int kb = 0; kb < 16; kb++) {
        if (kb < 15) { A_ISSUE(kb + 1); CP_WAIT1(); }
        else         { CP_WAIT0(); }
        __syncthreads();
        const uint32_t stg = sb + AST0 + (kb & 1) * ASTAGE;

        // ---- S = Q K^T over 64 keys ----
        float sacc[8][4];
        #pragma unroll
        for (int i = 0; i < 8; i++)
            #pragma unroll
            for (int j = 0; j < 4; j++) sacc[i][j] = 0.f;
        #pragma unroll
        for (int ks = 0; ks < 8; ks++) {
            uint32_t qh[4], ql[4];
            {
                int r = mbase + arow;
                int kc = ks * 2 + akc;
                uint32_t off = SW256((uint32_t)(r * 256 + kc * 16));
                ldsm_x4(sb + AQ_HI + off, qh);
                ldsm_x4(sb + AQ_LO + off, ql);
            }
            #pragma unroll
            for (int ng = 0; ng < 4; ng++) {
                uint32_t kh4[4], kl4[4];
                int r = ng * 16 + brow;
                int kc = ks * 2 + bkc;
                uint32_t off = SW256((uint32_t)(r * 256 + kc * 16));
                ldsm_x4(stg + AK_HI + off, kh4);
                ldsm_x4(stg + AK_LO + off, kl4);
                #pragma unroll
                for (int p = 0; p < 2; p++) {
                    mma16816(sacc[ng * 2 + p], qh, &kh4[p * 2]);
                    mma16816(sacc[ng * 2 + p], qh, &kl4[p * 2]);
                    mma16816(sacc[ng * 2 + p], ql, &kh4[p * 2]);
                }
            }
        }

        // ---- online softmax (rows r0 = mbase+(lane>>2), r0+8) ----
        float mx0 = -1e30f, mx1 = -1e30f;
        #pragma unroll
        for (int nt = 0; nt < 8; nt++) {
            sacc[nt][0] *= cscale; sacc[nt][1] *= cscale;
            sacc[nt][2] *= cscale; sacc[nt][3] *= cscale;
            mx0 = fmaxf(mx0, fmaxf(sacc[nt][0], sacc[nt][1]));
            mx1 = fmaxf(mx1, fmaxf(sacc[nt][2], sacc[nt][3]));
        }
        mx0 = fmaxf(mx0, __shfl_xor_sync(0xffffffffu, mx0, 1));
        mx0 = fmaxf(mx0, __shfl_xor_sync(0xffffffffu, mx0, 2));
        mx1 = fmaxf(mx1, __shfl_xor_sync(0xffffffffu, mx1, 1));
        mx1 = fmaxf(mx1, __shfl_xor_sync(0xffffffffu, mx1, 2));
        float mn0 = fmaxf(m0r, mx0), mn1 = fmaxf(m1r, mx1);
        float al0 = fast_exp2(m0r - mn0), al1 = fast_exp2(m1r - mn1);
        m0r = mn0; m1r = mn1;
        float s0 = 0.f, s1 = 0.f;
        #pragma unroll
        for (int nt = 0; nt < 8; nt++) {
            sacc[nt][0] = fast_exp2(sacc[nt][0] - mn0); s0 += sacc[nt][0];
            sacc[nt][1] = fast_exp2(sacc[nt][1] - mn0); s0 += sacc[nt][1];
            sacc[nt][2] = fast_exp2(sacc[nt][2] - mn1); s1 += sacc[nt][2];
            sacc[nt][3] = fast_exp2(sacc[nt][3] - mn1); s1 += sacc[nt][3];
        }
        s0 += __shfl_xor_sync(0xffffffffu, s0, 1);
        s0 += __shfl_xor_sync(0xffffffffu, s0, 2);
        s1 += __shfl_xor_sync(0xffffffffu, s1, 1);
        s1 += __shfl_xor_sync(0xffffffffu, s1, 2);
        l0r = l0r * al0 + s0;
        l1r = l1r * al1 + s1;
        #pragma unroll
        for (int od = 0; od < 16; od++) {
            oacc[od][0] *= al0; oacc[od][1] *= al0;
            oacc[od][2] *= al1; oacc[od][3] *= al1;
        }

        // ---- P repack: C-frag -> A-frag bf16 hi/lo ----
        uint32_t ph[4][4], pl[4][4];
        #pragma unroll
        for (int kk = 0; kk < 4; kk++) {
            int t0 = 2 * kk, t1 = 2 * kk + 1;
            split2(sacc[t0][0], sacc[t0][1], ph[kk][0], pl[kk][0]);
            split2(sacc[t0][2], sacc[t0][3], ph[kk][1], pl[kk][1]);
            split2(sacc[t1][0], sacc[t1][1], ph[kk][2], pl[kk][2]);
            split2(sacc[t1][2], sacc[t1][3], ph[kk][3], pl[kk][3]);
        }

        // ---- O += P V ----
        #pragma unroll
        for (int kk = 0; kk < 4; kk++) {
            #pragma unroll
            for (int dg = 0; dg < 8; dg++) {
                uint32_t vh4[4], vl4[4];
                int r = dg * 16 + brow;
                int kc = kk * 2 + bkc;
                uint32_t off = SW128((uint32_t)(r * 128 + kc * 16));
                ldsm_x4(stg + AV_HI + off, vh4);
                ldsm_x4(stg + AV_LO + off, vl4);
                #pragma unroll
                for (int p = 0; p < 2; p++) {
                    mma16816(oacc[dg * 2 + p], ph[kk], &vh4[p * 2]);
                    mma16816(oacc[dg * 2 + p], ph[kk], &vl4[p * 2]);
                    mma16816(oacc[dg * 2 + p], pl[kk], &vh4[p * 2]);
                }
            }
        }
        __syncthreads();
    }
    #undef A_ISSUE

    // ---- epilogue: O/l -> bf16 hi/lo ----
    float inv0 = 1.0f / l0r, inv1 = 1.0f / l1r;
    const int r0 = mbase + (lane >> 2);
    const int qcol = (lane & 3) * 2;
    #pragma unroll
    for (int dg = 0; dg < 16; dg++) {
        int c = dg * 8 + qcol;
        uint32_t hw, lw;
        split2(oacc[dg][0] * inv0, oacc[dg][1] * inv0, hw, lw);
        *(uint32_t*)((__nv_bfloat16*)OgH + (size_t)r0 * DV + c) = hw;
        *(uint32_t*)((__nv_bfloat16*)OgL + (size_t)r0 * DV + c) = lw;
        split2(oacc[dg][2] * inv1, oacc[dg][3] * inv1, hw, lw);
        *(uint32_t*)((__nv_bfloat16*)OgH + (size_t)(r0 + 8) * DV + c) = hw;
        *(uint32_t*)((__nv_bfloat16*)OgL + (size_t)(r0 + 8) * DV + c) = lw;
    }
}

// ======================= launch =======================
extern "C" void kernel_launch(void* const* d_in, const int* in_sizes, int n_in,
                              void* d_out, int out_size)
{
    const float* x  = (const float*)d_in[0];
    const float* Wq = (const float*)d_in[1];
    const float* bq = (const float*)d_in[2];
    const float* Wk = (const float*)d_in[3];
    const float* bk = (const float*)d_in[4];
    const float* Wv = (const float*)d_in[5];
    const float* bv = (const float*)d_in[6];
    const float* Wo = (const float*)d_in[7];
    const float* bo = (const float*)d_in[8];
    float* out = (float*)d_out;

    cudaFuncSetAttribute(attn_kernel, cudaFuncAttributeMaxDynamicSharedMemorySize, ATTN_SMEM);
    cudaFuncSetAttribute(gemm_kernel, cudaFuncAttributeMaxDynamicSharedMemorySize, G_SMEM);

    __nv_bfloat16 *xhi, *xlo, *ohi, *olo;
    cudaGetSymbolAddress((void**)&xhi, g_xhi);
    cudaGetSymbolAddress((void**)&xlo, g_xlo);
    cudaGetSymbolAddress((void**)&ohi, g_Ohi);
    cudaGetSymbolAddress((void**)&olo, g_Olo);

    prep_kernel<<<3328, 256>>>(x, Wq, Wk, Wv, Wo);
    gemm_kernel<<<dim3(10, 16), 256, G_SMEM>>>(xhi, xlo, bq, bk, bv, bo, out, 0);
    attn_kernel<<<dim3(SEQ / 128, HEADS, BATCH), 256, ATTN_SMEM>>>();
    gemm_kernel<<<dim3(8, 16), 256, G_SMEM>>>(ohi, olo, bq, bk, bv, bo, out, 1);
}

// round 6
// speedup vs baseline: 3.0518x; 1.3141x over previous
#include <cuda_runtime.h>
#include <cuda_bf16.h>
#include <cstdint>

#define BATCH 2
#define SEQ   1024
#define DM    1024
#define HEADS 8
#define DV    128

// ======================= scratch (static device arrays) =======================
__device__ __nv_bfloat16 g_xhi[BATCH * SEQ * DM];
__device__ __nv_bfloat16 g_xlo[BATCH * SEQ * DM];
// W^T (K-major): [0,1024)=Wq^T  [1024,1152)=Wk^T  [1152,1280)=Wv^T  [1280,2304)=Wo^T
#define WT_ROWS 2304
__device__ __nv_bfloat16 g_WThi[WT_ROWS * DM];
__device__ __nv_bfloat16 g_WTlo[WT_ROWS * DM];
__device__ __nv_bfloat16 g_Qhi[BATCH * SEQ * DM];
__device__ __nv_bfloat16 g_Qlo[BATCH * SEQ * DM];
__device__ __nv_bfloat16 g_Khi[BATCH * SEQ * DV];
__device__ __nv_bfloat16 g_Klo[BATCH * SEQ * DV];
__device__ __nv_bfloat16 g_Vthi[BATCH * DV * SEQ];   // [b][dv][key]
__device__ __nv_bfloat16 g_Vtlo[BATCH * DV * SEQ];
__device__ __nv_bfloat16 g_Ohi[BATCH * SEQ * DM];
__device__ __nv_bfloat16 g_Olo[BATCH * SEQ * DM];

// ======================= helpers =======================
__device__ __forceinline__ uint32_t smem_u32(const void* p) {
    uint32_t a;
    asm("{ .reg .u64 t; cvta.to.shared.u64 t, %1; cvt.u32.u64 %0, t; }" : "=r"(a) : "l"(p));
    return a;
}
#define SW128(off) ((off) ^ (((off) >> 3) & 0x70))
#define SW256(off) ((off) ^ (((off) >> 4) & 0x70))

__device__ __forceinline__ void ldsm_x4(uint32_t addr, uint32_t* r) {
    asm volatile("ldmatrix.sync.aligned.m8n8.x4.shared.b16 {%0,%1,%2,%3}, [%4];"
        : "=r"(r[0]), "=r"(r[1]), "=r"(r[2]), "=r"(r[3]) : "r"(addr));
}
__device__ __forceinline__ void mma16816(float* d, const uint32_t* a, const uint32_t* b) {
    asm volatile("mma.sync.aligned.m16n8k16.row.col.f32.bf16.bf16.f32 "
        "{%0,%1,%2,%3}, {%4,%5,%6,%7}, {%8,%9}, {%0,%1,%2,%3};"
        : "+f"(d[0]), "+f"(d[1]), "+f"(d[2]), "+f"(d[3])
        : "r"(a[0]), "r"(a[1]), "r"(a[2]), "r"(a[3]), "r"(b[0]), "r"(b[1]));
}
__device__ __forceinline__ void cpasync16(uint32_t dst, const void* src) {
    asm volatile("cp.async.cg.shared.global [%0], [%1], 16;" :: "r"(dst), "l"(src));
}
#define CP_COMMIT() asm volatile("cp.async.commit_group;" ::: "memory")
#define CP_WAIT0()  asm volatile("cp.async.wait_group 0;" ::: "memory")
#define CP_WAIT1()  asm volatile("cp.async.wait_group 1;" ::: "memory")
#define CP_WAIT2()  asm volatile("cp.async.wait_group 2;" ::: "memory")

__device__ __forceinline__ void split2(float x, float y, uint32_t& h, uint32_t& l) {
    asm("cvt.rn.bf16x2.f32 %0, %1, %2;" : "=r"(h) : "f"(y), "f"(x));
    float hx = __uint_as_float(h << 16);
    float hy = __uint_as_float(h & 0xffff0000u);
    asm("cvt.rn.bf16x2.f32 %0, %1, %2;" : "=r"(l) : "f"(y - hy), "f"(x - hx));
}
__device__ __forceinline__ float fast_exp2(float x) {
    float y; asm("ex2.approx.f32 %0, %1;" : "=f"(y) : "f"(x)); return y;
}

// ======================= prep: split x, transpose+split W =======================
__global__ void __launch_bounds__(256) prep_kernel(
    const float* __restrict__ x,  const float* __restrict__ Wq,
    const float* __restrict__ Wk, const float* __restrict__ Wv,
    const float* __restrict__ Wo)
{
    const int tid = threadIdx.x;
    const int bi = blockIdx.x;
    if (bi < 1024) {
        size_t base = (size_t)bi * 2048 + tid * 8;
        float4 a = *(const float4*)(x + base);
        float4 b = *(const float4*)(x + base + 4);
        uint32_t h0, l0, h1, l1, h2, l2, h3, l3;
        split2(a.x, a.y, h0, l0); split2(a.z, a.w, h1, l1);
        split2(b.x, b.y, h2, l2); split2(b.z, b.w, h3, l3);
        ((uint4*)g_xhi)[base >> 3] = make_uint4(h0, h1, h2, h3);
        ((uint4*)g_xlo)[base >> 3] = make_uint4(l0, l1, l2, l3);
        return;
    }
    int t = bi - 1024;
    const float* src; int N; int drow;
    if (t < 1024)      { src = Wq; N = 1024; drow = 0; }
    else if (t < 1152) { t -= 1024; src = Wk; N = 128;  drow = 1024; }
    else if (t < 1280) { t -= 1152; src = Wv; N = 128;  drow = 1152; }
    else               { t -= 1280; src = Wo; N = 1024; drow = 1280; }
    const int ntn = N >> 5;
    const int n0 = (t % ntn) * 32, k0 = (t / ntn) * 32;
    __shared__ float sm[32][33];
    const int tx = tid & 31, ty = tid >> 5;
    #pragma unroll
    for (int i = 0; i < 4; i++)
        sm[ty + 8 * i][tx] = src[(size_t)(k0 + ty + 8 * i) * N + n0 + tx];
    __syncthreads();
    #pragma unroll
    for (int i = 0; i < 4; i++) {
        int n = ty + 8 * i;
        float v = sm[tx][n];
        __nv_bfloat16 h = __float2bfloat16(v);
        size_t o = (size_t)(drow + n0 + n) * DM + k0 + tx;
        g_WThi[o] = h;
        g_WTlo[o] = __float2bfloat16(v - __bfloat162float(h));
    }
}

// ======================= mma.sync bf16-split GEMM core (3-stage, frag-pipelined) =======================
// MT in {64,128} rows; N tile 128; K = 1024 in 16 chunks of 64.
// EPI: 0=Q(bf16 hi/lo), 1=K(bf16 hi/lo), 2=V transposed, 3=float out.
template<int MT, int EPI>
__device__ __forceinline__ void gemm_body(
    const __nv_bfloat16* __restrict__ Ahi_g, const __nv_bfloat16* __restrict__ Alo_g,
    const __nv_bfloat16* __restrict__ Bhi_g, const __nv_bfloat16* __restrict__ Blo_g,
    int m0, int n0, const float* __restrict__ bias, float* __restrict__ outp)
{
    constexpr int A_REG = MT * 128;
    constexpr int B_REG = 16384;
    constexpr int STAGE = 2 * A_REG + 2 * B_REG;
    constexpr int MFRAG = MT / 64;          // m16 frags per warp
    constexpr int A_ITER = MT / 32;         // 16B units per thread per A region

    extern __shared__ char smem[];
    const uint32_t sb = smem_u32(smem);
    const int tid = threadIdx.x;
    const int wid = tid >> 5, lane = tid & 31;

    uint32_t aswo[A_ITER]; size_t agoff[A_ITER];
    #pragma unroll
    for (int i = 0; i < A_ITER; i++) {
        int u = tid + i * 256;
        int row = u >> 3, c16 = u & 7;
        aswo[i] = SW128((uint32_t)(row * 128 + c16 * 16));
        agoff[i] = (size_t)(m0 + row) * DM + c16 * 8;
    }
    uint32_t bswo[4]; size_t bgoff[4];
    #pragma unroll
    for (int i = 0; i < 4; i++) {
        int u = tid + i * 256;
        int row = u >> 3, c16 = u & 7;
        bswo[i] = SW128((uint32_t)(row * 128 + c16 * 16));
        bgoff[i] = (size_t)row * DM + c16 * 8;
    }

    #define GISSUE(kt_) do { \
        const uint32_t bs_ = sb + ((kt_) % 3) * STAGE; \
        const int k0_ = (kt_) * 64; \
        _Pragma("unroll") \
        for (int i = 0; i < A_ITER; i++) { \
            cpasync16(bs_ + aswo[i], Ahi_g + agoff[i] + k0_); \
            cpasync16(bs_ + A_REG + aswo[i], Alo_g + agoff[i] + k0_); \
        } \
        _Pragma("unroll") \
        for (int i = 0; i < 4; i++) { \
            cpasync16(bs_ + 2 * A_REG + bswo[i], Bhi_g + bgoff[i] + k0_); \
            cpasync16(bs_ + 2 * A_REG + B_REG + bswo[i], Blo_g + bgoff[i] + k0_); \
        } \
        CP_COMMIT(); \
    } while (0)

    const int wm = wid >> 1, wn = wid & 1;
    const int mbase = wm * (MT / 4), nbase = wn * 64;

    float acc[MFRAG][8][4];
    #pragma unroll
    for (int mt = 0; mt < MFRAG; mt++)
        #pragma unroll
        for (int nt = 0; nt < 8; nt++)
            #pragma unroll
            for (int j = 0; j < 4; j++) acc[mt][nt][j] = 0.f;

    const int arow = (lane & 7) + ((lane >> 3) & 1) * 8;
    const int akc  = (lane >> 4) & 1;
    const int brow = (lane & 7) + ((lane >> 4) & 1) * 8;
    const int bkc  = (lane >> 3) & 1;

    uint32_t ah[2][MFRAG][4], al[2][MFRAG][4], bh[2][4][4], bl[2][4][4];

    #define GLOADF(buf_, rb_, ks_) do { \
        _Pragma("unroll") \
        for (int mt = 0; mt < MFRAG; mt++) { \
            int r = mbase + mt * 16 + arow; \
            int ke = (ks_) * 16 + akc * 8; \
            uint32_t off = (uint32_t)(r * 128 + (((ke >> 3) ^ (r & 7)) << 4)); \
            ldsm_x4((rb_) + off, ah[buf_][mt]); \
            ldsm_x4((rb_) + A_REG + off, al[buf_][mt]); \
        } \
        _Pragma("unroll") \
        for (int nq = 0; nq < 4; nq++) { \
            int r = nbase + nq * 16 + brow; \
            int ke = (ks_) * 16 + bkc * 8; \
            uint32_t off = (uint32_t)(r * 128 + (((ke >> 3) ^ (r & 7)) << 4)); \
            ldsm_x4((rb_) + 2 * A_REG + off, bh[buf_][nq]); \
            ldsm_x4((rb_) + 2 * A_REG + B_REG + off, bl[buf_][nq]); \
        } \
    } while (0)

    GISSUE(0); GISSUE(1);

    #pragma unroll 1
    for (int kt = 0; kt < 16; kt++) {
        if (kt == 15) CP_WAIT0(); else CP_WAIT1();
        __syncthreads();
        if (kt < 14) GISSUE(kt + 2);
        const uint32_t rb = sb + (kt % 3) * STAGE;

        GLOADF(0, rb, 0);
        #pragma unroll
        for (int ks = 0; ks < 4; ks++) {
            if (ks < 3) GLOADF((ks + 1) & 1, rb, ks + 1);
            const int cb = ks & 1;
            #pragma unroll
            for (int mt = 0; mt < MFRAG; mt++)
                #pragma unroll
                for (int nt = 0; nt < 8; nt++) {
                    const uint32_t* bhp = &bh[cb][nt >> 1][(nt & 1) * 2];
                    const uint32_t* blp = &bl[cb][nt >> 1][(nt & 1) * 2];
                    mma16816(acc[mt][nt], ah[cb][mt], bhp);
                    mma16816(acc[mt][nt], ah[cb][mt], blp);
                    mma16816(acc[mt][nt], al[cb][mt], bhp);
                }
        }
    }
    #undef GISSUE
    #undef GLOADF

    // ---------------- epilogue ----------------
    const int qrow = lane >> 2, qcol = (lane & 3) * 2;
    #pragma unroll
    for (int mt = 0; mt < MFRAG; mt++) {
        #pragma unroll
        for (int nt = 0; nt < 8; nt++) {
            int c = nbase + nt * 8 + qcol;
            float b0 = bias[n0 + c], b1 = bias[n0 + c + 1];
            int r0 = m0 + mbase + mt * 16 + qrow;
            float v0 = acc[mt][nt][0] + b0, v1 = acc[mt][nt][1] + b1;
            float v2 = acc[mt][nt][2] + b0, v3 = acc[mt][nt][3] + b1;
            if constexpr (EPI == 3) {
                *(float2*)&outp[(size_t)r0 * DM + n0 + c] = make_float2(v0, v1);
                *(float2*)&outp[(size_t)(r0 + 8) * DM + n0 + c] = make_float2(v2, v3);
            } else if constexpr (EPI == 0) {
                uint32_t h, l;
                split2(v0, v1, h, l);
                *(uint32_t*)((__nv_bfloat16*)g_Qhi + (size_t)r0 * DM + n0 + c) = h;
                *(uint32_t*)((__nv_bfloat16*)g_Qlo + (size_t)r0 * DM + n0 + c) = l;
                split2(v2, v3, h, l);
                *(uint32_t*)((__nv_bfloat16*)g_Qhi + (size_t)(r0 + 8) * DM + n0 + c) = h;
                *(uint32_t*)((__nv_bfloat16*)g_Qlo + (size_t)(r0 + 8) * DM + n0 + c) = l;
            } else if constexpr (EPI == 1) {
                uint32_t h, l;
                split2(v0, v1, h, l);
                *(uint32_t*)((__nv_bfloat16*)g_Khi + (size_t)r0 * DV + c) = h;
                *(uint32_t*)((__nv_bfloat16*)g_Klo + (size_t)r0 * DV + c) = l;
                split2(v2, v3, h, l);
                *(uint32_t*)((__nv_bfloat16*)g_Khi + (size_t)(r0 + 8) * DV + c) = h;
                *(uint32_t*)((__nv_bfloat16*)g_Klo + (size_t)(r0 + 8) * DV + c) = l;
            } else {   // EPI == 2: V transposed [b][dv][key]
                float vals[4] = {v0, v1, v2, v3};
                #pragma unroll
                for (int j = 0; j < 4; j++) {
                    int row = r0 + (j >> 1) * 8;
                    int col = c + (j & 1);
                    int bb = row >> 10, key = row & 1023;
                    size_t o = (size_t)bb * (DV * SEQ) + (size_t)col * SEQ + key;
                    __nv_bfloat16 hh = __float2bfloat16(vals[j]);
                    g_Vthi[o] = hh;
                    g_Vtlo[o] = __float2bfloat16(vals[j] - __bfloat162float(hh));
                }
            }
        }
    }
}

#define G128_SMEM (3 * (2 * 128 * 128 + 2 * 16384))   // 196608
#define G64_SMEM  (3 * (2 * 64 * 128 + 2 * 16384))    // 147456

__global__ void __launch_bounds__(256, 1) kv_kernel(const float* __restrict__ bk,
                                                    const float* __restrict__ bv)
{
    const int m0 = blockIdx.y * 64;
    if (blockIdx.x == 0)
        gemm_body<64, 1>(g_xhi, g_xlo, g_WThi + (size_t)1024 * DM, g_WTlo + (size_t)1024 * DM,
                         m0, 0, bk, nullptr);
    else
        gemm_body<64, 2>(g_xhi, g_xlo, g_WThi + (size_t)1152 * DM, g_WTlo + (size_t)1152 * DM,
                         m0, 0, bv, nullptr);
}
__global__ void __launch_bounds__(256, 1) q_kernel(const float* __restrict__ bq)
{
    const size_t wrow = (size_t)blockIdx.x * 128;
    gemm_body<128, 0>(g_xhi, g_xlo, g_WThi + wrow * DM, g_WTlo + wrow * DM,
                      blockIdx.y * 128, blockIdx.x * 128, bq, nullptr);
}
__global__ void __launch_bounds__(256, 1) o_kernel(const float* __restrict__ bo,
                                                   float* __restrict__ out)
{
    const size_t wrow = 1280 + (size_t)blockIdx.x * 128;
    gemm_body<128, 3>(g_Ohi, g_Olo, g_WThi + wrow * DM, g_WTlo + wrow * DM,
                      blockIdx.y * 128, blockIdx.x * 128, bo, out);
}

// ======================= flash attention (mma.sync, Q-frag hoist, 3-stage) =======================
// CTA = (qb,h,b): 128 q-rows x 1024 keys; 8 warps, warp = 16 q-rows.
// 3 regions of 64KB: stage s -> region s%3. Region layout: Khi 0, Klo 16K, Vhi 32K, Vlo 48K.
// Q loads into region 2 first (Qhi +0, Qlo +32K), hoisted to regs, region recycled at kb=0.
#define AREG   65536
#define ATTN_SMEM (3 * AREG)

__global__ void __launch_bounds__(256, 1) attn_kernel()
{
    extern __shared__ char smem[];
    const uint32_t sb = smem_u32(smem);
    const int tid = threadIdx.x;
    const int wid = tid >> 5, lane = tid & 31;
    const int qb = blockIdx.x, h = blockIdx.y, b = blockIdx.z;

    const __nv_bfloat16* Qh = g_Qhi + (size_t)b * (SEQ * DM) + h * (SEQ * DV) + qb * (128 * DV);
    const __nv_bfloat16* Ql = g_Qlo + (size_t)b * (SEQ * DM) + h * (SEQ * DV) + qb * (128 * DV);
    const __nv_bfloat16* Kh = g_Khi + (size_t)b * (SEQ * DV);
    const __nv_bfloat16* Kl = g_Klo + (size_t)b * (SEQ * DV);
    const __nv_bfloat16* Vh = g_Vthi + (size_t)b * (DV * SEQ);
    const __nv_bfloat16* Vl = g_Vtlo + (size_t)b * (DV * SEQ);
    __nv_bfloat16* OgH = g_Ohi + (size_t)b * (SEQ * DM) + h * (SEQ * DV) + qb * (128 * DV);
    __nv_bfloat16* OgL = g_Olo + (size_t)b * (SEQ * DM) + h * (SEQ * DV) + qb * (128 * DV);

    // ---- Q load into region 2 (group 0) ----
    #pragma unroll
    for (int i = 0; i < 8; i++) {
        int id = tid + i * 256;
        int row = id >> 4, kc = id & 15;
        uint32_t d = SW256((uint32_t)(row * 256 + kc * 16));
        cpasync16(sb + 2 * AREG + d, Qh + row * 128 + kc * 8);
        cpasync16(sb + 2 * AREG + 32768 + d, Ql + row * 128 + kc * 8);
    }
    CP_COMMIT();

    #define A_ISSUE(s_) do { \
        const uint32_t base_ = sb + ((s_) % 3) * AREG; \
        const int k0_ = (s_) * 64; \
        _Pragma("unroll") \
        for (int i = 0; i < 4; i++) { \
            int id = tid + i * 256; \
            int kr = id >> 4, kcc = id & 15; \
            uint32_t dk = SW256((uint32_t)(kr * 256 + kcc * 16)); \
            cpasync16(base_ + dk, Kh + (size_t)(k0_ + kr) * 128 + kcc * 8); \
            cpasync16(base_ + 16384 + dk, Kl + (size_t)(k0_ + kr) * 128 + kcc * 8); \
            int vr = id >> 3, vc = id & 7; \
            uint32_t dv_ = SW128((uint32_t)(vr * 128 + vc * 16)); \
            cpasync16(base_ + 32768 + dv_, Vh + (size_t)vr * 1024 + k0_ + vc * 8); \
            cpasync16(base_ + 49152 + dv_, Vl + (size_t)vr * 1024 + k0_ + vc * 8); \
        } \
        CP_COMMIT(); \
    } while (0)

    A_ISSUE(0);   // group 1
    A_ISSUE(1);   // group 2

    const int mbase = wid * 16;
    const int arow = (lane & 7) + ((lane >> 3) & 1) * 8;
    const int akc  = (lane >> 4) & 1;
    const int brow = (lane & 7) + ((lane >> 4) & 1) * 8;
    const int bkc  = (lane >> 3) & 1;

    // ---- hoist Q fragments ----
    CP_WAIT2();          // group 0 (Q) complete
    __syncthreads();
    uint32_t qfh[8][4], qfl[8][4];
    #pragma unroll
    for (int ks = 0; ks < 8; ks++) {
        int r = mbase + arow;
        int kc = ks * 2 + akc;
        uint32_t off = SW256((uint32_t)(r * 256 + kc * 16));
        ldsm_x4(sb + 2 * AREG + off, qfh[ks]);
        ldsm_x4(sb + 2 * AREG + 32768 + off, qfl[ks]);
    }

    float oacc[16][4];
    #pragma unroll
    for (int i = 0; i < 16; i++)
        #pragma unroll
        for (int j = 0; j < 4; j++) oacc[i][j] = 0.f;
    float m0r = -1e30f, m1r = -1e30f, l0r = 0.f, l1r = 0.f;

    const float cscale = 0.08838834764831845f * 1.4426950408889634f;

    #pragma unroll 1
    for (int kb = 0; kb < 16; kb++) {
        if (kb == 15) CP_WAIT0(); else CP_WAIT1();
        __syncthreads();              // rendezvous: everyone done with stage kb-1 reads; stage kb visible
        if (kb < 14) A_ISSUE(kb + 2); // writes region (kb+2)%3 — safe (distance 2 behind reads)
        const uint32_t stg = sb + (kb % 3) * AREG;

        // ---- S = Q K^T over 64 keys ----
        float sacc[8][4];
        #pragma unroll
        for (int i = 0; i < 8; i++)
            #pragma unroll
            for (int j = 0; j < 4; j++) sacc[i][j] = 0.f;
        #pragma unroll
        for (int ks = 0; ks < 8; ks++) {
            #pragma unroll
            for (int ng = 0; ng < 4; ng++) {
                uint32_t kh4[4], kl4[4];
                int r = ng * 16 + brow;
                int kc = ks * 2 + bkc;
                uint32_t off = SW256((uint32_t)(r * 256 + kc * 16));
                ldsm_x4(stg + off, kh4);
                ldsm_x4(stg + 16384 + off, kl4);
                #pragma unroll
                for (int p = 0; p < 2; p++) {
                    mma16816(sacc[ng * 2 + p], qfh[ks], &kh4[p * 2]);
                    mma16816(sacc[ng * 2 + p], qfh[ks], &kl4[p * 2]);
                    mma16816(sacc[ng * 2 + p], qfl[ks], &kh4[p * 2]);
                }
            }
        }

        // ---- online softmax ----
        float mx0 = -1e30f, mx1 = -1e30f;
        #pragma unroll
        for (int nt = 0; nt < 8; nt++) {
            sacc[nt][0] *= cscale; sacc[nt][1] *= cscale;
            sacc[nt][2] *= cscale; sacc[nt][3] *= cscale;
            mx0 = fmaxf(mx0, fmaxf(sacc[nt][0], sacc[nt][1]));
            mx1 = fmaxf(mx1, fmaxf(sacc[nt][2], sacc[nt][3]));
        }
        mx0 = fmaxf(mx0, __shfl_xor_sync(0xffffffffu, mx0, 1));
        mx0 = fmaxf(mx0, __shfl_xor_sync(0xffffffffu, mx0, 2));
        mx1 = fmaxf(mx1, __shfl_xor_sync(0xffffffffu, mx1, 1));
        mx1 = fmaxf(mx1, __shfl_xor_sync(0xffffffffu, mx1, 2));
        float mn0 = fmaxf(m0r, mx0), mn1 = fmaxf(m1r, mx1);
        float al0 = fast_exp2(m0r - mn0), al1 = fast_exp2(m1r - mn1);
        m0r = mn0; m1r = mn1;
        float s0 = 0.f, s1 = 0.f;
        #pragma unroll
        for (int nt = 0; nt < 8; nt++) {
            sacc[nt][0] = fast_exp2(sacc[nt][0] - mn0); s0 += sacc[nt][0];
            sacc[nt][1] = fast_exp2(sacc[nt][1] - mn0); s0 += sacc[nt][1];
            sacc[nt][2] = fast_exp2(sacc[nt][2] - mn1); s1 += sacc[nt][2];
            sacc[nt][3] = fast_exp2(sacc[nt][3] - mn1); s1 += sacc[nt][3];
        }
        s0 += __shfl_xor_sync(0xffffffffu, s0, 1);
        s0 += __shfl_xor_sync(0xffffffffu, s0, 2);
        s1 += __shfl_xor_sync(0xffffffffu, s1, 1);
        s1 += __shfl_xor_sync(0xffffffffu, s1, 2);
        l0r = l0r * al0 + s0;
        l1r = l1r * al1 + s1;
        #pragma unroll
        for (int od = 0; od < 16; od++) {
            oacc[od][0] *= al0; oacc[od][1] *= al0;
            oacc[od][2] *= al1; oacc[od][3] *= al1;
        }

        // ---- P repack: C-frag -> A-frag bf16 hi/lo ----
        uint32_t ph[4][4], pl[4][4];
        #pragma unroll
        for (int kk = 0; kk < 4; kk++) {
            int t0 = 2 * kk, t1 = 2 * kk + 1;
            split2(sacc[t0][0], sacc[t0][1], ph[kk][0], pl[kk][0]);
            split2(sacc[t0][2], sacc[t0][3], ph[kk][1], pl[kk][1]);
            split2(sacc[t1][0], sacc[t1][1], ph[kk][2], pl[kk][2]);
            split2(sacc[t1][2], sacc[t1][3], ph[kk][3], pl[kk][3]);
        }

        // ---- O += P V ----
        #pragma unroll
        for (int kk = 0; kk < 4; kk++) {
            #pragma unroll
            for (int dg = 0; dg < 8; dg++) {
                uint32_t vh4[4], vl4[4];
                int r = dg * 16 + brow;
                int kc = kk * 2 + bkc;
                uint32_t off = SW128((uint32_t)(r * 128 + kc * 16));
                ldsm_x4(stg + 32768 + off, vh4);
                ldsm_x4(stg + 49152 + off, vl4);
                #pragma unroll
                for (int p = 0; p < 2; p++) {
                    mma16816(oacc[dg * 2 + p], ph[kk], &vh4[p * 2]);
                    mma16816(oacc[dg * 2 + p], ph[kk], &vl4[p * 2]);
                    mma16816(oacc[dg * 2 + p], pl[kk], &vh4[p * 2]);
                }
            }
        }
    }
    #undef A_ISSUE

    // ---- epilogue: O/l -> bf16 hi/lo ----
    float inv0 = 1.0f / l0r, inv1 = 1.0f / l1r;
    const int r0 = mbase + (lane >> 2);
    const int qcol = (lane & 3) * 2;
    #pragma unroll
    for (int dg = 0; dg < 16; dg++) {
        int c = dg * 8 + qcol;
        uint32_t hw, lw;
        split2(oacc[dg][0] * inv0, oacc[dg][1] * inv0, hw, lw);
        *(uint32_t*)((__nv_bfloat16*)OgH + (size_t)r0 * DV + c) = hw;
        *(uint32_t*)((__nv_bfloat16*)OgL + (size_t)r0 * DV + c) = lw;
        split2(oacc[dg][2] * inv1, oacc[dg][3] * inv1, hw, lw);
        *(uint32_t*)((__nv_bfloat16*)OgH + (size_t)(r0 + 8) * DV + c) = hw;
        *(uint32_t*)((__nv_bfloat16*)OgL + (size_t)(r0 + 8) * DV + c) = lw;
    }
}

// ======================= launch =======================
extern "C" void kernel_launch(void* const* d_in, const int* in_sizes, int n_in,
                              void* d_out, int out_size)
{
    const float* x  = (const float*)d_in[0];
    const float* Wq = (const float*)d_in[1];
    const float* bq = (const float*)d_in[2];
    const float* Wk = (const float*)d_in[3];
    const float* bk = (const float*)d_in[4];
    const float* Wv = (const float*)d_in[5];
    const float* bv = (const float*)d_in[6];
    const float* Wo = (const float*)d_in[7];
    const float* bo = (const float*)d_in[8];
    float* out = (float*)d_out;

    cudaFuncSetAttribute(attn_kernel, cudaFuncAttributeMaxDynamicSharedMemorySize, ATTN_SMEM);
    cudaFuncSetAttribute(kv_kernel,  cudaFuncAttributeMaxDynamicSharedMemorySize, G64_SMEM);
    cudaFuncSetAttribute(q_kernel,   cudaFuncAttributeMaxDynamicSharedMemorySize, G128_SMEM);
    cudaFuncSetAttribute(o_kernel,   cudaFuncAttributeMaxDynamicSharedMemorySize, G128_SMEM);

    prep_kernel<<<3328, 256>>>(x, Wq, Wk, Wv, Wo);
    kv_kernel<<<dim3(2, 32), 256, G64_SMEM>>>(bk, bv);
    q_kernel<<<dim3(8, 16), 256, G128_SMEM>>>(bq);
    attn_kernel<<<dim3(SEQ / 128, HEADS, BATCH), 256, ATTN_SMEM>>>();
    o_kernel<<<dim3(8, 16), 256, G128_SMEM>>>(bo, out);
}